// round 1
// baseline (speedup 1.0000x reference)
#include <cuda_runtime.h>
#include <math_constants.h>

#define HD 1024      // hidden dim
#define MM 4096      // memory slots
#define NR 8192      // B*S rows
#define TK 64        // top-k
#define THRESHF 0.5f

// ---------------- scratch (static device globals; no runtime alloc) ----------
__device__ float g_norm[NR * HD];                 // 32 MB
__device__ float g_surprise[NR];
__device__ float g_mem[MM * HD];                  // 16 MB
__device__ float g_q[NR * HD];                    // 32 MB
__device__ float g_sim[NR * MM];                  // 128 MB
__device__ float g_ret[NR * HD];                  // 32 MB
__device__ int   g_top_idx[TK];
__device__ float g_top_val[TK];
__device__ int   g_slots[TK];
__device__ float g_slot_val[TK];

// ---------------- LayerNorm + surprise --------------------------------------
__global__ void ln_kernel(const float* __restrict__ x,
                          const float* __restrict__ gam,
                          const float* __restrict__ bet) {
    __shared__ float sh[256];
    const int row = blockIdx.x;
    const int t = threadIdx.x;
    const float* xr = x + (size_t)row * HD;

    float v[4];
    float s = 0.f;
#pragma unroll
    for (int i = 0; i < 4; i++) { v[i] = xr[t + i * 256]; s += v[i]; }
    sh[t] = s; __syncthreads();
    for (int o = 128; o > 0; o >>= 1) { if (t < o) sh[t] += sh[t + o]; __syncthreads(); }
    const float mu = sh[0] * (1.f / HD);
    __syncthreads();

    float ss = 0.f;
#pragma unroll
    for (int i = 0; i < 4; i++) { float d = v[i] - mu; ss += d * d; }
    sh[t] = ss; __syncthreads();
    for (int o = 128; o > 0; o >>= 1) { if (t < o) sh[t] += sh[t + o]; __syncthreads(); }
    const float var = sh[0] * (1.f / HD);
    __syncthreads();

    const float inv = rsqrtf(var + 1e-12f);
    float* nr = g_norm + (size_t)row * HD;
    float as = 0.f;
#pragma unroll
    for (int i = 0; i < 4; i++) {
        const int c = t + i * 256;
        const float y = (v[i] - mu) * inv * gam[c] + bet[c];
        nr[c] = y;
        as += fabsf(y);
    }
    sh[t] = as; __syncthreads();
    for (int o = 128; o > 0; o >>= 1) { if (t < o) sh[t] += sh[t + o]; __syncthreads(); }
    if (t == 0) g_surprise[row] = sh[0] * (1.f / HD);
}

// ---------------- top-K (selection via repeated argmax; ties -> lowest idx) --
template <int PER, bool NEG>
__device__ void topk_impl(const float* __restrict__ src,
                          int* __restrict__ oidx, float* __restrict__ oval) {
    __shared__ float sv[1024];
    __shared__ int   si[1024];
    const int t = threadIdx.x;
    float loc[PER];
#pragma unroll
    for (int i = 0; i < PER; i++) {
        float x = src[t * PER + i];
        loc[i] = NEG ? -x : x;
    }
    for (int k = 0; k < TK; k++) {
        float bv = -CUDART_INF_F; int bi = 0x7fffffff;
#pragma unroll
        for (int i = 0; i < PER; i++) {
            if (loc[i] > bv) { bv = loc[i]; bi = t * PER + i; }
        }
        sv[t] = bv; si[t] = bi; __syncthreads();
        for (int o = 512; o > 0; o >>= 1) {
            if (t < o) {
                float ov = sv[t + o]; int oi = si[t + o];
                if (ov > sv[t] || (ov == sv[t] && oi < si[t])) { sv[t] = ov; si[t] = oi; }
            }
            __syncthreads();
        }
        const int win = si[0];
        if (t == 0) { oidx[k] = win; oval[k] = NEG ? -sv[0] : sv[0]; }
        __syncthreads();   // everyone has read si[0]/sv[0] before next overwrite
        const int rel = win - t * PER;
        if ((unsigned)rel < (unsigned)PER) loc[rel] = -CUDART_INF_F;
    }
}

__global__ void topk_surprise_kernel() {
    topk_impl<NR / 1024, false>(g_surprise, g_top_idx, g_top_val);
}
__global__ void topk_slots_kernel(const float* __restrict__ imp) {
    topk_impl<MM / 1024, true>(imp, g_slots, g_slot_val);
}

// ---------------- memory materialization ------------------------------------
__global__ void copy_mem_kernel(const float* __restrict__ memin) {
    const int row = blockIdx.x, t = threadIdx.x;
    const float4 v = *reinterpret_cast<const float4*>(memin + (size_t)row * HD + t * 4);
    *reinterpret_cast<float4*>(g_mem + (size_t)row * HD + t * 4) = v;
}
__global__ void scatter_mem_kernel() {
    const int j = blockIdx.x;
    if (g_top_val[j] <= THRESHF) return;
    const int src = g_top_idx[j];
    const int dst = g_slots[j];
    const int t = threadIdx.x;
    const float4 v = *reinterpret_cast<const float4*>(g_norm + (size_t)src * HD + t * 4);
    *reinterpret_cast<float4*>(g_mem + (size_t)dst * HD + t * 4) = v;
}

// ---------------- SGEMM: 128x128x8 tile, 8x8/thread (4+4 split) --------------
// C[M,N] = A[M,K] * op(B)   where op(B)=B^T if TRANSB (B is [N,K]) else B is [K,N]
// optional +bias[N], +res[M,N]
template <bool TRANSB, bool BIAS, bool RES>
__global__ __launch_bounds__(256) void sgemm_kernel(
    const float* __restrict__ A, const float* __restrict__ B,
    const float* __restrict__ bias, const float* __restrict__ res,
    float* __restrict__ C, int Mq, int Nq, int Kq) {
    __shared__ float As[8][128];
    __shared__ float Bs[8][128];
    const int t  = threadIdx.x;
    const int tx = t & 15, ty = t >> 4;
    const int m0 = blockIdx.y * 128, n0 = blockIdx.x * 128;

    float acc[8][8];
#pragma unroll
    for (int i = 0; i < 8; i++)
#pragma unroll
        for (int j = 0; j < 8; j++) acc[i][j] = 0.f;

    const int lrow = t >> 1;         // 0..127
    const int lk   = (t & 1) * 4;    // 0 or 4
    const float* Aptr = A + (size_t)(m0 + lrow) * Kq + lk;

    const float* Bptr;
    int bk = 0, bn4 = 0;
    if (TRANSB) {
        Bptr = B + (size_t)(n0 + lrow) * Kq + lk;
    } else {
        bk = t >> 5; bn4 = (t & 31) * 4;
        Bptr = B + (size_t)bk * Nq + n0 + bn4;
    }

    for (int k0 = 0; k0 < Kq; k0 += 8) {
        const float4 a4 = *reinterpret_cast<const float4*>(Aptr + k0);
        As[lk + 0][lrow] = a4.x; As[lk + 1][lrow] = a4.y;
        As[lk + 2][lrow] = a4.z; As[lk + 3][lrow] = a4.w;
        if (TRANSB) {
            const float4 b4 = *reinterpret_cast<const float4*>(Bptr + k0);
            Bs[lk + 0][lrow] = b4.x; Bs[lk + 1][lrow] = b4.y;
            Bs[lk + 2][lrow] = b4.z; Bs[lk + 3][lrow] = b4.w;
        } else {
            const float4 b4 = *reinterpret_cast<const float4*>(Bptr + (size_t)k0 * Nq);
            *reinterpret_cast<float4*>(&Bs[bk][bn4]) = b4;
        }
        __syncthreads();
#pragma unroll
        for (int kk = 0; kk < 8; kk++) {
            const float4 a0 = *reinterpret_cast<const float4*>(&As[kk][ty * 4]);
            const float4 a1 = *reinterpret_cast<const float4*>(&As[kk][64 + ty * 4]);
            const float4 b0 = *reinterpret_cast<const float4*>(&Bs[kk][tx * 4]);
            const float4 b1 = *reinterpret_cast<const float4*>(&Bs[kk][64 + tx * 4]);
            const float ra[8] = {a0.x, a0.y, a0.z, a0.w, a1.x, a1.y, a1.z, a1.w};
            const float rb[8] = {b0.x, b0.y, b0.z, b0.w, b1.x, b1.y, b1.z, b1.w};
#pragma unroll
            for (int i = 0; i < 8; i++)
#pragma unroll
                for (int j = 0; j < 8; j++)
                    acc[i][j] = fmaf(ra[i], rb[j], acc[i][j]);
        }
        __syncthreads();
    }

#pragma unroll
    for (int i = 0; i < 8; i++) {
        const int r = m0 + ((i < 4) ? (ty * 4 + i) : (64 + ty * 4 + (i - 4)));
#pragma unroll
        for (int jh = 0; jh < 2; jh++) {
            const int c = n0 + ((jh == 0) ? (tx * 4) : (64 + tx * 4));
            float4 v = make_float4(acc[i][jh * 4 + 0], acc[i][jh * 4 + 1],
                                   acc[i][jh * 4 + 2], acc[i][jh * 4 + 3]);
            if (BIAS) {
                v.x += bias[c + 0]; v.y += bias[c + 1];
                v.z += bias[c + 2]; v.w += bias[c + 3];
            }
            if (RES) {
                const float4 rr = *reinterpret_cast<const float4*>(res + (size_t)r * Nq + c);
                v.x += rr.x; v.y += rr.y; v.z += rr.z; v.w += rr.w;
            }
            *reinterpret_cast<float4*>(C + (size_t)r * Nq + c) = v;
        }
    }
}

// ---------------- row softmax over M=4096 ------------------------------------
__global__ void softmax_kernel() {
    __shared__ float sh[256];
    const int row = blockIdx.x, t = threadIdx.x;
    float* p = g_sim + (size_t)row * MM;
    float v[16];
    float mx = -CUDART_INF_F;
#pragma unroll
    for (int i = 0; i < 16; i++) { v[i] = p[t + i * 256]; mx = fmaxf(mx, v[i]); }
    sh[t] = mx; __syncthreads();
    for (int o = 128; o > 0; o >>= 1) { if (t < o) sh[t] = fmaxf(sh[t], sh[t + o]); __syncthreads(); }
    mx = sh[0]; __syncthreads();
    float s = 0.f;
#pragma unroll
    for (int i = 0; i < 16; i++) { v[i] = expf(v[i] - mx); s += v[i]; }
    sh[t] = s; __syncthreads();
    for (int o = 128; o > 0; o >>= 1) { if (t < o) sh[t] += sh[t + o]; __syncthreads(); }
    const float inv = 1.f / sh[0];
#pragma unroll
    for (int i = 0; i < 16; i++) p[t + i * 256] = v[i] * inv;
}

// ---------------- launch ------------------------------------------------------
extern "C" void kernel_launch(void* const* d_in, const int* in_sizes, int n_in,
                              void* d_out, int out_size) {
    const float* hidden = (const float*)d_in[0];
    const float* gam    = (const float*)d_in[1];
    const float* bet    = (const float*)d_in[2];
    const float* Wq     = (const float*)d_in[3];
    const float* bq     = (const float*)d_in[4];
    const float* Wo     = (const float*)d_in[5];
    const float* bo     = (const float*)d_in[6];
    const float* memin  = (const float*)d_in[7];
    const float* imp    = (const float*)d_in[8];
    float* out = (float*)d_out;

    float *p_norm, *p_q, *p_sim, *p_ret, *p_mem;
    cudaGetSymbolAddress((void**)&p_norm, g_norm);
    cudaGetSymbolAddress((void**)&p_q,    g_q);
    cudaGetSymbolAddress((void**)&p_sim,  g_sim);
    cudaGetSymbolAddress((void**)&p_ret,  g_ret);
    cudaGetSymbolAddress((void**)&p_mem,  g_mem);

    // 1) LayerNorm + surprise
    ln_kernel<<<NR, 256>>>(hidden, gam, bet);
    // 2) top-64 surprises (desc) and 64 least-important slots (asc)
    topk_surprise_kernel<<<1, 1024>>>();
    topk_slots_kernel<<<1, 1024>>>(imp);
    // 3) materialize updated memory
    copy_mem_kernel<<<MM, 256>>>(memin);
    scatter_mem_kernel<<<TK, 256>>>();
    // 4) q = norm @ Wq^T + bq
    {
        dim3 g(HD / 128, NR / 128);
        sgemm_kernel<true, true, false><<<g, 256>>>(p_norm, Wq, bq, nullptr, p_q, NR, HD, HD);
    }
    // 5) sim = q @ mem^T
    {
        dim3 g(MM / 128, NR / 128);
        sgemm_kernel<true, false, false><<<g, 256>>>(p_q, p_mem, nullptr, nullptr, p_sim, NR, MM, HD);
    }
    // 6) softmax rows
    softmax_kernel<<<NR, 256>>>();
    // 7) retrieved = attn @ mem
    {
        dim3 g(HD / 128, NR / 128);
        sgemm_kernel<false, false, false><<<g, 256>>>(p_sim, p_mem, nullptr, nullptr, p_ret, NR, HD, MM);
    }
    // 8) out = retrieved @ Wo^T + bo + hidden
    {
        dim3 g(HD / 128, NR / 128);
        sgemm_kernel<true, true, true><<<g, 256>>>(p_ret, Wo, bo, hidden, out, NR, HD, HD);
    }
}

// round 2
// speedup vs baseline: 1.0012x; 1.0012x over previous
#include <cuda_runtime.h>
#include <math_constants.h>

#define HD 1024      // hidden dim
#define MM 4096      // memory slots
#define NR 8192      // B*S rows
#define TK 64        // top-k
#define THRESHF 0.5f

// ---------------- scratch (static device globals; no runtime alloc) ----------
__device__ float g_norm[NR * HD];                 // 32 MB
__device__ float g_surprise[NR];
__device__ float g_mem[MM * HD];                  // 16 MB
__device__ float g_q[NR * HD];                    // 32 MB
__device__ float g_sim[NR * MM];                  // 128 MB
__device__ float g_ret[NR * HD];                  // 32 MB
__device__ int   g_top_idx[TK];
__device__ float g_top_val[TK];
__device__ int   g_slots[TK];
__device__ float g_slot_val[TK];

// ---------------- LayerNorm + surprise --------------------------------------
__global__ void ln_kernel(const float* __restrict__ x,
                          const float* __restrict__ gam,
                          const float* __restrict__ bet) {
    __shared__ float sh[256];
    const int row = blockIdx.x;
    const int t = threadIdx.x;
    const float* xr = x + (size_t)row * HD;

    float v[4];
    float s = 0.f;
#pragma unroll
    for (int i = 0; i < 4; i++) { v[i] = xr[t + i * 256]; s += v[i]; }
    sh[t] = s; __syncthreads();
    for (int o = 128; o > 0; o >>= 1) { if (t < o) sh[t] += sh[t + o]; __syncthreads(); }
    const float mu = sh[0] * (1.f / HD);
    __syncthreads();

    float ss = 0.f;
#pragma unroll
    for (int i = 0; i < 4; i++) { float d = v[i] - mu; ss += d * d; }
    sh[t] = ss; __syncthreads();
    for (int o = 128; o > 0; o >>= 1) { if (t < o) sh[t] += sh[t + o]; __syncthreads(); }
    const float var = sh[0] * (1.f / HD);
    __syncthreads();

    const float inv = rsqrtf(var + 1e-12f);
    float* nr = g_norm + (size_t)row * HD;
    float as = 0.f;
#pragma unroll
    for (int i = 0; i < 4; i++) {
        const int c = t + i * 256;
        const float y = (v[i] - mu) * inv * gam[c] + bet[c];
        nr[c] = y;
        as += fabsf(y);
    }
    sh[t] = as; __syncthreads();
    for (int o = 128; o > 0; o >>= 1) { if (t < o) sh[t] += sh[t + o]; __syncthreads(); }
    if (t == 0) g_surprise[row] = sh[0] * (1.f / HD);
}

// ---------------- top-K (selection via repeated argmax; ties -> lowest idx) --
template <int PER, bool NEG>
__device__ void topk_impl(const float* __restrict__ src,
                          int* __restrict__ oidx, float* __restrict__ oval) {
    __shared__ float sv[1024];
    __shared__ int   si[1024];
    const int t = threadIdx.x;
    float loc[PER];
#pragma unroll
    for (int i = 0; i < PER; i++) {
        float x = src[t * PER + i];
        loc[i] = NEG ? -x : x;
    }
    for (int k = 0; k < TK; k++) {
        float bv = -CUDART_INF_F; int bi = 0x7fffffff;
#pragma unroll
        for (int i = 0; i < PER; i++) {
            if (loc[i] > bv) { bv = loc[i]; bi = t * PER + i; }
        }
        sv[t] = bv; si[t] = bi; __syncthreads();
        for (int o = 512; o > 0; o >>= 1) {
            if (t < o) {
                float ov = sv[t + o]; int oi = si[t + o];
                if (ov > sv[t] || (ov == sv[t] && oi < si[t])) { sv[t] = ov; si[t] = oi; }
            }
            __syncthreads();
        }
        const int win = si[0];
        if (t == 0) { oidx[k] = win; oval[k] = NEG ? -sv[0] : sv[0]; }
        __syncthreads();   // everyone has read si[0]/sv[0] before next overwrite
        const int rel = win - t * PER;
        if ((unsigned)rel < (unsigned)PER) loc[rel] = -CUDART_INF_F;
    }
}

__global__ void topk_surprise_kernel() {
    topk_impl<NR / 1024, false>(g_surprise, g_top_idx, g_top_val);
}
__global__ void topk_slots_kernel(const float* __restrict__ imp) {
    topk_impl<MM / 1024, true>(imp, g_slots, g_slot_val);
}

// ---------------- memory materialization ------------------------------------
__global__ void copy_mem_kernel(const float* __restrict__ memin) {
    const int row = blockIdx.x, t = threadIdx.x;
    const float4 v = *reinterpret_cast<const float4*>(memin + (size_t)row * HD + t * 4);
    *reinterpret_cast<float4*>(g_mem + (size_t)row * HD + t * 4) = v;
}
__global__ void scatter_mem_kernel() {
    const int j = blockIdx.x;
    if (g_top_val[j] <= THRESHF) return;
    const int src = g_top_idx[j];
    const int dst = g_slots[j];
    const int t = threadIdx.x;
    const float4 v = *reinterpret_cast<const float4*>(g_norm + (size_t)src * HD + t * 4);
    *reinterpret_cast<float4*>(g_mem + (size_t)dst * HD + t * 4) = v;
}

// ---------------- SGEMM: 128x128x8 tile, 8x8/thread (4+4 split) --------------
// C[M,N] = A[M,K] * op(B)   where op(B)=B^T if TRANSB (B is [N,K]) else B is [K,N]
// optional +bias[N], +res[M,N]
template <bool TRANSB, bool BIAS, bool RES>
__global__ __launch_bounds__(256) void sgemm_kernel(
    const float* __restrict__ A, const float* __restrict__ B,
    const float* __restrict__ bias, const float* __restrict__ res,
    float* __restrict__ C, int Mq, int Nq, int Kq) {
    __shared__ float As[8][128];
    __shared__ float Bs[8][128];
    const int t  = threadIdx.x;
    const int tx = t & 15, ty = t >> 4;
    const int m0 = blockIdx.y * 128, n0 = blockIdx.x * 128;

    float acc[8][8];
#pragma unroll
    for (int i = 0; i < 8; i++)
#pragma unroll
        for (int j = 0; j < 8; j++) acc[i][j] = 0.f;

    const int lrow = t >> 1;         // 0..127
    const int lk   = (t & 1) * 4;    // 0 or 4
    const float* Aptr = A + (size_t)(m0 + lrow) * Kq + lk;

    const float* Bptr;
    int bk = 0, bn4 = 0;
    if (TRANSB) {
        Bptr = B + (size_t)(n0 + lrow) * Kq + lk;
    } else {
        bk = t >> 5; bn4 = (t & 31) * 4;
        Bptr = B + (size_t)bk * Nq + n0 + bn4;
    }

    for (int k0 = 0; k0 < Kq; k0 += 8) {
        const float4 a4 = *reinterpret_cast<const float4*>(Aptr + k0);
        As[lk + 0][lrow] = a4.x; As[lk + 1][lrow] = a4.y;
        As[lk + 2][lrow] = a4.z; As[lk + 3][lrow] = a4.w;
        if (TRANSB) {
            const float4 b4 = *reinterpret_cast<const float4*>(Bptr + k0);
            Bs[lk + 0][lrow] = b4.x; Bs[lk + 1][lrow] = b4.y;
            Bs[lk + 2][lrow] = b4.z; Bs[lk + 3][lrow] = b4.w;
        } else {
            const float4 b4 = *reinterpret_cast<const float4*>(Bptr + (size_t)k0 * Nq);
            *reinterpret_cast<float4*>(&Bs[bk][bn4]) = b4;
        }
        __syncthreads();
#pragma unroll
        for (int kk = 0; kk < 8; kk++) {
            const float4 a0 = *reinterpret_cast<const float4*>(&As[kk][ty * 4]);
            const float4 a1 = *reinterpret_cast<const float4*>(&As[kk][64 + ty * 4]);
            const float4 b0 = *reinterpret_cast<const float4*>(&Bs[kk][tx * 4]);
            const float4 b1 = *reinterpret_cast<const float4*>(&Bs[kk][64 + tx * 4]);
            const float ra[8] = {a0.x, a0.y, a0.z, a0.w, a1.x, a1.y, a1.z, a1.w};
            const float rb[8] = {b0.x, b0.y, b0.z, b0.w, b1.x, b1.y, b1.z, b1.w};
#pragma unroll
            for (int i = 0; i < 8; i++)
#pragma unroll
                for (int j = 0; j < 8; j++)
                    acc[i][j] = fmaf(ra[i], rb[j], acc[i][j]);
        }
        __syncthreads();
    }

#pragma unroll
    for (int i = 0; i < 8; i++) {
        const int r = m0 + ((i < 4) ? (ty * 4 + i) : (64 + ty * 4 + (i - 4)));
#pragma unroll
        for (int jh = 0; jh < 2; jh++) {
            const int c = n0 + ((jh == 0) ? (tx * 4) : (64 + tx * 4));
            float4 v = make_float4(acc[i][jh * 4 + 0], acc[i][jh * 4 + 1],
                                   acc[i][jh * 4 + 2], acc[i][jh * 4 + 3]);
            if (BIAS) {
                v.x += bias[c + 0]; v.y += bias[c + 1];
                v.z += bias[c + 2]; v.w += bias[c + 3];
            }
            if (RES) {
                const float4 rr = *reinterpret_cast<const float4*>(res + (size_t)r * Nq + c);
                v.x += rr.x; v.y += rr.y; v.z += rr.z; v.w += rr.w;
            }
            *reinterpret_cast<float4*>(C + (size_t)r * Nq + c) = v;
        }
    }
}

// ---------------- row softmax over M=4096 ------------------------------------
__global__ void softmax_kernel() {
    __shared__ float sh[256];
    const int row = blockIdx.x, t = threadIdx.x;
    float* p = g_sim + (size_t)row * MM;
    float v[16];
    float mx = -CUDART_INF_F;
#pragma unroll
    for (int i = 0; i < 16; i++) { v[i] = p[t + i * 256]; mx = fmaxf(mx, v[i]); }
    sh[t] = mx; __syncthreads();
    for (int o = 128; o > 0; o >>= 1) { if (t < o) sh[t] = fmaxf(sh[t], sh[t + o]); __syncthreads(); }
    mx = sh[0]; __syncthreads();
    float s = 0.f;
#pragma unroll
    for (int i = 0; i < 16; i++) { v[i] = expf(v[i] - mx); s += v[i]; }
    sh[t] = s; __syncthreads();
    for (int o = 128; o > 0; o >>= 1) { if (t < o) sh[t] += sh[t + o]; __syncthreads(); }
    const float inv = 1.f / sh[0];
#pragma unroll
    for (int i = 0; i < 16; i++) p[t + i * 256] = v[i] * inv;
}

// ---------------- launch ------------------------------------------------------
extern "C" void kernel_launch(void* const* d_in, const int* in_sizes, int n_in,
                              void* d_out, int out_size) {
    const float* hidden = (const float*)d_in[0];
    const float* gam    = (const float*)d_in[1];
    const float* bet    = (const float*)d_in[2];
    const float* Wq     = (const float*)d_in[3];
    const float* bq     = (const float*)d_in[4];
    const float* Wo     = (const float*)d_in[5];
    const float* bo     = (const float*)d_in[6];
    const float* memin  = (const float*)d_in[7];
    const float* imp    = (const float*)d_in[8];
    float* out = (float*)d_out;

    float *p_norm, *p_q, *p_sim, *p_ret, *p_mem;
    cudaGetSymbolAddress((void**)&p_norm, g_norm);
    cudaGetSymbolAddress((void**)&p_q,    g_q);
    cudaGetSymbolAddress((void**)&p_sim,  g_sim);
    cudaGetSymbolAddress((void**)&p_ret,  g_ret);
    cudaGetSymbolAddress((void**)&p_mem,  g_mem);

    // 1) LayerNorm + surprise
    ln_kernel<<<NR, 256>>>(hidden, gam, bet);
    // 2) top-64 surprises (desc) and 64 least-important slots (asc)
    topk_surprise_kernel<<<1, 1024>>>();
    topk_slots_kernel<<<1, 1024>>>(imp);
    // 3) materialize updated memory
    copy_mem_kernel<<<MM, 256>>>(memin);
    scatter_mem_kernel<<<TK, 256>>>();
    // 4) q = norm @ Wq^T + bq
    {
        dim3 g(HD / 128, NR / 128);
        sgemm_kernel<true, true, false><<<g, 256>>>(p_norm, Wq, bq, nullptr, p_q, NR, HD, HD);
    }
    // 5) sim = q @ mem^T
    {
        dim3 g(MM / 128, NR / 128);
        sgemm_kernel<true, false, false><<<g, 256>>>(p_q, p_mem, nullptr, nullptr, p_sim, NR, MM, HD);
    }
    // 6) softmax rows
    softmax_kernel<<<NR, 256>>>();
    // 7) retrieved = attn @ mem
    {
        dim3 g(HD / 128, NR / 128);
        sgemm_kernel<false, false, false><<<g, 256>>>(p_sim, p_mem, nullptr, nullptr, p_ret, NR, HD, MM);
    }
    // 8) out = retrieved @ Wo^T + bo + hidden
    {
        dim3 g(HD / 128, NR / 128);
        sgemm_kernel<true, true, true><<<g, 256>>>(p_ret, Wo, bo, hidden, out, NR, HD, HD);
    }
}

// round 4
// speedup vs baseline: 2.6457x; 2.6426x over previous
#include <cuda_runtime.h>
#include <cstdint>
#include <math_constants.h>

#define HD 1024
#define MMR 4096
#define NR 8192
#define TK 64
#define THRESHF 0.5f

// ---------------- scratch globals ---------------------------------------------
__device__ float g_nhi[(size_t)NR * HD];
__device__ float g_nlo[(size_t)NR * HD];
__device__ float g_mem[(size_t)MMR * HD];
__device__ float g_memT[(size_t)HD * MMR];
__device__ float g_q[(size_t)NR * HD];
__device__ float g_sim[(size_t)NR * MMR];
__device__ float g_attn[(size_t)NR * MMR];
__device__ float g_ret[(size_t)NR * HD];
__device__ float g_wqhi[(size_t)HD * HD];
__device__ float g_wqlo[(size_t)HD * HD];
__device__ float g_wo[(size_t)HD * HD];
__device__ float g_surprise[NR];
__device__ int   g_top_idx[TK];
__device__ float g_top_val[TK];
__device__ int   g_slots[TK];
__device__ float g_slot_val[TK];

// ---------------- helpers -------------------------------------------------------
__device__ __forceinline__ uint32_t smem_u32(const void* p) {
    uint32_t a;
    asm("{ .reg .u64 t; cvta.to.shared.u64 t, %1; cvt.u32.u64 %0, t; }" : "=r"(a) : "l"(p));
    return a;
}
__device__ __forceinline__ float to_tf32(float x) {
    float r; asm("cvt.rna.tf32.f32 %0, %1;" : "=f"(r) : "f"(x)); return r;
}
__device__ __forceinline__ void cp16(uint32_t so, const void* gp) {
    asm volatile("cp.async.cg.shared.global [%0], [%1], 16;" :: "r"(so), "l"(gp) : "memory");
}
#define CP_COMMIT() asm volatile("cp.async.commit_group;" ::: "memory")
#define CP_WAIT1()  asm volatile("cp.async.wait_group 1;" ::: "memory")

__device__ __forceinline__ void mma8(float* d, const uint32_t* a, uint32_t b0, uint32_t b1) {
    asm volatile(
        "mma.sync.aligned.m16n8k8.row.col.f32.tf32.tf32.f32 "
        "{%0,%1,%2,%3}, {%4,%5,%6,%7}, {%8,%9}, {%0,%1,%2,%3};"
        : "+f"(d[0]), "+f"(d[1]), "+f"(d[2]), "+f"(d[3])
        : "r"(a[0]), "r"(a[1]), "r"(a[2]), "r"(a[3]), "r"(b0), "r"(b1));
}

__device__ __forceinline__ float fexp(float x) {   // e^x on the FMA pipe
    float t = fmaxf(x * 1.44269504088896340736f, -126.f);
    float n = rintf(t);
    float f = t - n;
    float p = 1.8775767e-3f;
    p = fmaf(p, f, 8.9893397e-3f);
    p = fmaf(p, f, 5.5826318e-2f);
    p = fmaf(p, f, 2.4015361e-1f);
    p = fmaf(p, f, 6.9315308e-1f);
    p = fmaf(p, f, 1.0f);
    return p * __int_as_float(((int)n + 127) << 23);
}

// ---------------- LayerNorm + surprise + tf32 split -----------------------------
__global__ void ln_kernel(const float* __restrict__ x,
                          const float* __restrict__ gam,
                          const float* __restrict__ bet) {
    __shared__ float sh[256];
    const int row = blockIdx.x, t = threadIdx.x;
    const float* xr = x + (size_t)row * HD;
    float v[4]; float s = 0.f;
#pragma unroll
    for (int i = 0; i < 4; i++) { v[i] = xr[t + i * 256]; s += v[i]; }
    sh[t] = s; __syncthreads();
    for (int o = 128; o > 0; o >>= 1) { if (t < o) sh[t] += sh[t + o]; __syncthreads(); }
    const float mu = sh[0] * (1.f / HD);
    __syncthreads();
    float ss = 0.f;
#pragma unroll
    for (int i = 0; i < 4; i++) { float d = v[i] - mu; ss += d * d; }
    sh[t] = ss; __syncthreads();
    for (int o = 128; o > 0; o >>= 1) { if (t < o) sh[t] += sh[t + o]; __syncthreads(); }
    const float var = sh[0] * (1.f / HD);
    __syncthreads();
    const float inv = rsqrtf(var + 1e-12f);
    float as = 0.f;
#pragma unroll
    for (int i = 0; i < 4; i++) {
        const int c = t + i * 256;
        const float y = (v[i] - mu) * inv * gam[c] + bet[c];
        const float hi = to_tf32(y);
        g_nhi[(size_t)row * HD + c] = hi;
        g_nlo[(size_t)row * HD + c] = to_tf32(y - hi);
        as += fabsf(y);
    }
    sh[t] = as; __syncthreads();
    for (int o = 128; o > 0; o >>= 1) { if (t < o) sh[t] += sh[t + o]; __syncthreads(); }
    if (t == 0) g_surprise[row] = sh[0] * (1.f / HD);
}

// ---------------- top-K ----------------------------------------------------------
template <int PER, bool NEG>
__device__ void topk_impl(const float* __restrict__ src,
                          int* __restrict__ oidx, float* __restrict__ oval) {
    __shared__ float sv[1024];
    __shared__ int   si[1024];
    const int t = threadIdx.x;
    float loc[PER];
#pragma unroll
    for (int i = 0; i < PER; i++) { float x = src[t * PER + i]; loc[i] = NEG ? -x : x; }
    for (int k = 0; k < TK; k++) {
        float bv = -CUDART_INF_F; int bi = 0x7fffffff;
#pragma unroll
        for (int i = 0; i < PER; i++)
            if (loc[i] > bv) { bv = loc[i]; bi = t * PER + i; }
        sv[t] = bv; si[t] = bi; __syncthreads();
        for (int o = 512; o > 0; o >>= 1) {
            if (t < o) {
                float ov = sv[t + o]; int oi = si[t + o];
                if (ov > sv[t] || (ov == sv[t] && oi < si[t])) { sv[t] = ov; si[t] = oi; }
            }
            __syncthreads();
        }
        const int win = si[0];
        if (t == 0) { oidx[k] = win; oval[k] = NEG ? -sv[0] : sv[0]; }
        __syncthreads();
        const int rel = win - t * PER;
        if ((unsigned)rel < (unsigned)PER) loc[rel] = -CUDART_INF_F;
    }
}
__global__ void topk_surprise_kernel() { topk_impl<NR / 1024, false>(g_surprise, g_top_idx, g_top_val); }
__global__ void topk_slots_kernel(const float* __restrict__ imp) { topk_impl<MMR / 1024, true>(imp, g_slots, g_slot_val); }

// ---------------- elementwise prep ------------------------------------------------
__global__ void round_kernel(const float* __restrict__ src, float* __restrict__ dst, int n4) {
    const int i = blockIdx.x * blockDim.x + threadIdx.x;
    if (i >= n4) return;
    float4 v = reinterpret_cast<const float4*>(src)[i];
    v.x = to_tf32(v.x); v.y = to_tf32(v.y); v.z = to_tf32(v.z); v.w = to_tf32(v.w);
    reinterpret_cast<float4*>(dst)[i] = v;
}
__global__ void split_kernel(const float* __restrict__ src,
                             float* __restrict__ hi, float* __restrict__ lo, int n4) {
    const int i = blockIdx.x * blockDim.x + threadIdx.x;
    if (i >= n4) return;
    float4 v = reinterpret_cast<const float4*>(src)[i];
    float4 h, l;
    h.x = to_tf32(v.x); l.x = to_tf32(v.x - h.x);
    h.y = to_tf32(v.y); l.y = to_tf32(v.y - h.y);
    h.z = to_tf32(v.z); l.z = to_tf32(v.z - h.z);
    h.w = to_tf32(v.w); l.w = to_tf32(v.w - h.w);
    reinterpret_cast<float4*>(hi)[i] = h;
    reinterpret_cast<float4*>(lo)[i] = l;
}
__global__ void scatter_mem_kernel() {
    const int j = blockIdx.x;
    if (g_top_val[j] <= THRESHF) return;
    const int src = g_top_idx[j], dst = g_slots[j];
    const int t = threadIdx.x;
    const float4 h = *reinterpret_cast<const float4*>(g_nhi + (size_t)src * HD + t * 4);
    *reinterpret_cast<float4*>(g_mem + (size_t)dst * HD + t * 4) = h;
}
// transpose mem[MMR][HD] -> memT[HD][MMR]
__global__ void transpose_kernel(const float* __restrict__ in, float* __restrict__ out) {
    __shared__ float tile[32][33];
    const int tx = threadIdx.x, ty = threadIdx.y;
    const int h0 = blockIdx.x * 32, m0 = blockIdx.y * 32;
#pragma unroll
    for (int k = 0; k < 4; k++)
        tile[ty + k * 8][tx] = in[(size_t)(m0 + ty + k * 8) * HD + h0 + tx];
    __syncthreads();
#pragma unroll
    for (int k = 0; k < 4; k++)
        out[(size_t)(h0 + ty + k * 8) * MMR + m0 + tx] = tile[tx][ty + k * 8];
}

// ---------------- softmax: g_sim -> rounded g_attn ---------------------------------
__global__ void softmax_kernel() {
    __shared__ float sh[256];
    const int row = blockIdx.x, t = threadIdx.x;
    const float* p = g_sim + (size_t)row * MMR;
    float v[16];
    float mx = -CUDART_INF_F;
#pragma unroll
    for (int i = 0; i < 16; i++) { v[i] = p[t + i * 256]; mx = fmaxf(mx, v[i]); }
    sh[t] = mx; __syncthreads();
    for (int o = 128; o > 0; o >>= 1) { if (t < o) sh[t] = fmaxf(sh[t], sh[t + o]); __syncthreads(); }
    mx = sh[0]; __syncthreads();
    float s = 0.f;
#pragma unroll
    for (int i = 0; i < 16; i++) { v[i] = fexp(v[i] - mx); s += v[i]; }
    sh[t] = s; __syncthreads();
    for (int o = 128; o > 0; o >>= 1) { if (t < o) sh[t] += sh[t + o]; __syncthreads(); }
    const float inv = 1.f / sh[0];
#pragma unroll
    for (int i = 0; i < 16; i++)
        g_attn[(size_t)row * MMR + t + i * 256] = to_tf32(v[i] * inv);
}

// ---------------- mma.sync tf32 GEMM -------------------------------------------------
// C[M,N] = A[M,K] * B[N,K]^T, both K-major. SPLITQ: 3-product split (Ah+Al)(Bh+Bl).
#define PAD 36
#define TILE_FLOATS (128 * PAD)

__device__ __forceinline__ void g2s_tile(const float* __restrict__ g, int ld,
                                         int row0, int k0, float* __restrict__ s, int tid) {
#pragma unroll
    for (int j = 0; j < 4; j++) {
        const int idx = j * 256 + tid;
        const int r = idx >> 3, c = idx & 7;
        cp16(smem_u32(s + r * PAD + c * 4), g + (size_t)(row0 + r) * ld + k0 + c * 4);
    }
}

template <bool SPLITQ, bool BIAS, bool RES, bool ROUND>
__global__ __launch_bounds__(256, 2) void mma_gemm(
    const float* __restrict__ Ah, const float* __restrict__ Al,
    const float* __restrict__ Bh, const float* __restrict__ Bl,
    float* __restrict__ C, const float* __restrict__ bias, const float* __restrict__ res,
    int Nq, int Kq) {
    extern __shared__ float sm[];
    const int NT = SPLITQ ? 4 : 2;
    const int tid = threadIdx.x;
    const int lane = tid & 31, warp = tid >> 5;
    const int gq = lane >> 2, cq = lane & 3;
    const int wm = (warp >> 1) * 32, wn = (warp & 1) * 64;
    const int m0 = blockIdx.y * 128, n0 = blockIdx.x * 128;
    const int nc = Kq >> 5;

    float acc[2][8][4];
#pragma unroll
    for (int mi = 0; mi < 2; mi++)
#pragma unroll
        for (int ni = 0; ni < 8; ni++)
#pragma unroll
            for (int r = 0; r < 4; r++) acc[mi][ni][r] = 0.f;

    // prologue: stages 0,1
#pragma unroll
    for (int p = 0; p < 2; p++) {
        float* base = sm + p * NT * TILE_FLOATS;
        g2s_tile(Ah, Kq, m0, p * 32, base, tid);
        g2s_tile(Bh, Kq, n0, p * 32, base + TILE_FLOATS, tid);
        if (SPLITQ) {
            g2s_tile(Al, Kq, m0, p * 32, base + 2 * TILE_FLOATS, tid);
            g2s_tile(Bl, Kq, n0, p * 32, base + 3 * TILE_FLOATS, tid);
        }
        CP_COMMIT();
    }

    for (int i = 0; i < nc; i++) {
        CP_WAIT1();
        __syncthreads();
        const int s = i & 1;
        const float* base = sm + s * NT * TILE_FLOATS;
        const uint32_t* sA  = reinterpret_cast<const uint32_t*>(base);
        const uint32_t* sB  = reinterpret_cast<const uint32_t*>(base + TILE_FLOATS);
        const uint32_t* sAl = reinterpret_cast<const uint32_t*>(base + 2 * TILE_FLOATS);
        const uint32_t* sBl = reinterpret_cast<const uint32_t*>(base + 3 * TILE_FLOATS);
#pragma unroll
        for (int ks = 0; ks < 4; ks++) {
            const int kc = ks * 8 + cq;
            uint32_t a[2][4], al[2][4];
#pragma unroll
            for (int mi = 0; mi < 2; mi++) {
                const uint32_t* ap = sA + (wm + mi * 16 + gq) * PAD + kc;
                a[mi][0] = ap[0]; a[mi][1] = ap[8 * PAD];
                a[mi][2] = ap[4]; a[mi][3] = ap[8 * PAD + 4];
                if (SPLITQ) {
                    const uint32_t* ap2 = sAl + (wm + mi * 16 + gq) * PAD + kc;
                    al[mi][0] = ap2[0]; al[mi][1] = ap2[8 * PAD];
                    al[mi][2] = ap2[4]; al[mi][3] = ap2[8 * PAD + 4];
                }
            }
#pragma unroll
            for (int ni = 0; ni < 8; ni++) {
                const uint32_t* bp = sB + (wn + ni * 8 + gq) * PAD + kc;
                const uint32_t b0 = bp[0], b1 = bp[4];
#pragma unroll
                for (int mi = 0; mi < 2; mi++) mma8(acc[mi][ni], a[mi], b0, b1);
                if (SPLITQ) {
                    const uint32_t* bp2 = sBl + (wn + ni * 8 + gq) * PAD + kc;
                    const uint32_t bl0 = bp2[0], bl1 = bp2[4];
#pragma unroll
                    for (int mi = 0; mi < 2; mi++) {
                        mma8(acc[mi][ni], a[mi], bl0, bl1);
                        mma8(acc[mi][ni], al[mi], b0, b1);
                    }
                }
            }
        }
        __syncthreads();
        if (i + 2 < nc) {
            float* wbase = sm + s * NT * TILE_FLOATS;
            g2s_tile(Ah, Kq, m0, (i + 2) * 32, wbase, tid);
            g2s_tile(Bh, Kq, n0, (i + 2) * 32, wbase + TILE_FLOATS, tid);
            if (SPLITQ) {
                g2s_tile(Al, Kq, m0, (i + 2) * 32, wbase + 2 * TILE_FLOATS, tid);
                g2s_tile(Bl, Kq, n0, (i + 2) * 32, wbase + 3 * TILE_FLOATS, tid);
            }
        }
        CP_COMMIT();
    }

    // epilogue
#pragma unroll
    for (int mi = 0; mi < 2; mi++) {
#pragma unroll
        for (int ni = 0; ni < 8; ni++) {
            const int row = m0 + wm + mi * 16 + gq;
            const int col = n0 + wn + ni * 8 + 2 * cq;
            float2 v0 = make_float2(acc[mi][ni][0], acc[mi][ni][1]);
            float2 v1 = make_float2(acc[mi][ni][2], acc[mi][ni][3]);
            if (BIAS) {
                const float2 bb = *reinterpret_cast<const float2*>(bias + col);
                v0.x += bb.x; v0.y += bb.y; v1.x += bb.x; v1.y += bb.y;
            }
            if (RES) {
                const float2 r0 = *reinterpret_cast<const float2*>(res + (size_t)row * Nq + col);
                const float2 r1 = *reinterpret_cast<const float2*>(res + (size_t)(row + 8) * Nq + col);
                v0.x += r0.x; v0.y += r0.y; v1.x += r1.x; v1.y += r1.y;
            }
            if (ROUND) {
                v0.x = to_tf32(v0.x); v0.y = to_tf32(v0.y);
                v1.x = to_tf32(v1.x); v1.y = to_tf32(v1.y);
            }
            *reinterpret_cast<float2*>(C + (size_t)row * Nq + col) = v0;
            *reinterpret_cast<float2*>(C + (size_t)(row + 8) * Nq + col) = v1;
        }
    }
}

// ---------------- launch ----------------------------------------------------------
#define SMEM_N (2 * 2 * TILE_FLOATS * 4)   // 73728
#define SMEM_S (2 * 4 * TILE_FLOATS * 4)   // 147456

extern "C" void kernel_launch(void* const* d_in, const int* in_sizes, int n_in,
                              void* d_out, int out_size) {
    const float* hidden = (const float*)d_in[0];
    const float* gam    = (const float*)d_in[1];
    const float* bet    = (const float*)d_in[2];
    const float* Wq     = (const float*)d_in[3];
    const float* bq     = (const float*)d_in[4];
    const float* Wo     = (const float*)d_in[5];
    const float* bo     = (const float*)d_in[6];
    const float* memin  = (const float*)d_in[7];
    const float* imp    = (const float*)d_in[8];
    float* out = (float*)d_out;

    float *p_nhi, *p_nlo, *p_mem, *p_memT, *p_q, *p_sim, *p_attn, *p_ret;
    float *p_wqhi, *p_wqlo, *p_wo;
    cudaGetSymbolAddress((void**)&p_nhi, g_nhi);   cudaGetSymbolAddress((void**)&p_nlo, g_nlo);
    cudaGetSymbolAddress((void**)&p_mem, g_mem);   cudaGetSymbolAddress((void**)&p_memT, g_memT);
    cudaGetSymbolAddress((void**)&p_q, g_q);       cudaGetSymbolAddress((void**)&p_sim, g_sim);
    cudaGetSymbolAddress((void**)&p_attn, g_attn); cudaGetSymbolAddress((void**)&p_ret, g_ret);
    cudaGetSymbolAddress((void**)&p_wqhi, g_wqhi); cudaGetSymbolAddress((void**)&p_wqlo, g_wqlo);
    cudaGetSymbolAddress((void**)&p_wo, g_wo);

    cudaFuncSetAttribute((const void*)mma_gemm<true, true, false, true>,
                         cudaFuncAttributeMaxDynamicSharedMemorySize, SMEM_S);
    cudaFuncSetAttribute((const void*)mma_gemm<false, false, false, false>,
                         cudaFuncAttributeMaxDynamicSharedMemorySize, SMEM_N);
    cudaFuncSetAttribute((const void*)mma_gemm<false, false, false, true>,
                         cudaFuncAttributeMaxDynamicSharedMemorySize, SMEM_N);
    cudaFuncSetAttribute((const void*)mma_gemm<false, true, true, false>,
                         cudaFuncAttributeMaxDynamicSharedMemorySize, SMEM_N);

    // 1) LayerNorm (writes split norm) + surprise
    ln_kernel<<<NR, 256>>>(hidden, gam, bet);
    // 2) top-K selections
    topk_surprise_kernel<<<1, 1024>>>();
    topk_slots_kernel<<<1, 1024>>>(imp);
    // 3) memory: rounded copy, scatter updates, transpose
    round_kernel<<<(MMR * HD / 4 + 255) / 256, 256>>>(memin, p_mem, MMR * HD / 4);
    scatter_mem_kernel<<<TK, 256>>>();
    {
        dim3 b(32, 8), g(HD / 32, MMR / 32);
        transpose_kernel<<<g, b>>>(p_mem, p_memT);
    }
    // 4) weights
    split_kernel<<<(HD * HD / 4 + 255) / 256, 256>>>(Wq, p_wqhi, p_wqlo, HD * HD / 4);
    round_kernel<<<(HD * HD / 4 + 255) / 256, 256>>>(Wo, p_wo, HD * HD / 4);
    // 5) q = norm @ Wq^T + bq   (split tf32, rounded output)
    {
        dim3 g(HD / 128, NR / 128);
        mma_gemm<true, true, false, true><<<g, 256, SMEM_S>>>(
            p_nhi, p_nlo, p_wqhi, p_wqlo, p_q, bq, nullptr, HD, HD);
    }
    // 6) sim = q @ mem^T
    {
        dim3 g(MMR / 128, NR / 128);
        mma_gemm<false, false, false, false><<<g, 256, SMEM_N>>>(
            p_q, nullptr, p_mem, nullptr, p_sim, nullptr, nullptr, MMR, HD);
    }
    // 7) softmax -> rounded attn
    softmax_kernel<<<NR, 256>>>();
    // 8) retrieved = attn @ mem  (B = memT, rounded output)
    {
        dim3 g(HD / 128, NR / 128);
        mma_gemm<false, false, false, true><<<g, 256, SMEM_N>>>(
            p_attn, nullptr, p_memT, nullptr, p_ret, nullptr, nullptr, HD, MMR);
    }
    // 9) out = retrieved @ Wo^T + bo + hidden
    {
        dim3 g(HD / 128, NR / 128);
        mma_gemm<false, true, true, false><<<g, 256, SMEM_N>>>(
            p_ret, nullptr, p_wo, nullptr, out, bo, hidden, HD, HD);
    }
}

// round 5
// speedup vs baseline: 3.0358x; 1.1474x over previous
#include <cuda_runtime.h>
#include <cstdint>
#include <math_constants.h>

#define HD 1024
#define MMR 4096
#define NR 8192
#define TK 64
#define THRESHF 0.5f

// ---------------- scratch globals ---------------------------------------------
__device__ float g_nhi[(size_t)NR * HD];
__device__ float g_nlo[(size_t)NR * HD];
__device__ float g_mhi[(size_t)MMR * HD];
__device__ float g_mlo[(size_t)MMR * HD];
__device__ float g_wqThi[(size_t)HD * HD];
__device__ float g_wqTlo[(size_t)HD * HD];
__device__ float g_wohi[(size_t)HD * HD];
__device__ float g_wolo[(size_t)HD * HD];
__device__ float g_w2[(size_t)MMR * HD];    // mem @ Wq       [MMR, HD]
__device__ float g_w3[(size_t)MMR * HD];    // mem @ Wo^T     [MMR, HD]
__device__ float g_w3T[(size_t)HD * MMR];
__device__ float g_sim[(size_t)NR * MMR];   // logits, then attn in-place
__device__ float g_cvec[MMR];
__device__ float g_surprise[NR];
__device__ int   g_top_idx[TK];
__device__ float g_top_val[TK];
__device__ int   g_slots[TK];
__device__ float g_slot_val[TK];

// ---------------- helpers -------------------------------------------------------
__device__ __forceinline__ uint32_t smem_u32(const void* p) {
    uint32_t a;
    asm("{ .reg .u64 t; cvta.to.shared.u64 t, %1; cvt.u32.u64 %0, t; }" : "=r"(a) : "l"(p));
    return a;
}
__device__ __forceinline__ float to_tf32(float x) {
    float r; asm("cvt.rna.tf32.f32 %0, %1;" : "=f"(r) : "f"(x)); return r;
}
__device__ __forceinline__ void cp16(uint32_t so, const void* gp) {
    asm volatile("cp.async.cg.shared.global [%0], [%1], 16;" :: "r"(so), "l"(gp) : "memory");
}
#define CP_COMMIT() asm volatile("cp.async.commit_group;" ::: "memory")
#define CP_WAIT1()  asm volatile("cp.async.wait_group 1;" ::: "memory")

__device__ __forceinline__ void mma8(float* d, const uint32_t* a, uint32_t b0, uint32_t b1) {
    asm volatile(
        "mma.sync.aligned.m16n8k8.row.col.f32.tf32.tf32.f32 "
        "{%0,%1,%2,%3}, {%4,%5,%6,%7}, {%8,%9}, {%0,%1,%2,%3};"
        : "+f"(d[0]), "+f"(d[1]), "+f"(d[2]), "+f"(d[3])
        : "r"(a[0]), "r"(a[1]), "r"(a[2]), "r"(a[3]), "r"(b0), "r"(b1));
}

__device__ __forceinline__ float fexp(float x) {   // e^x on the FMA pipe
    float t = fmaxf(x * 1.44269504088896340736f, -126.f);
    float n = rintf(t);
    float f = t - n;
    float p = 1.8775767e-3f;
    p = fmaf(p, f, 8.9893397e-3f);
    p = fmaf(p, f, 5.5826318e-2f);
    p = fmaf(p, f, 2.4015361e-1f);
    p = fmaf(p, f, 6.9315308e-1f);
    p = fmaf(p, f, 1.0f);
    return p * __int_as_float(((int)n + 127) << 23);
}

// ---------------- weight prep: Wq^T split + Wo split ------------------------------
__global__ void weight_prep(const float* __restrict__ Wq, const float* __restrict__ Wo) {
    __shared__ float tile[32][33];
    const int tx = threadIdx.x, ty = threadIdx.y;
    const int c0 = blockIdx.x * 32, r0 = blockIdx.y * 32;
    if (blockIdx.z == 0) {
#pragma unroll
        for (int k = 0; k < 4; k++)
            tile[ty + k * 8][tx] = Wq[(size_t)(r0 + ty + k * 8) * HD + c0 + tx];
        __syncthreads();
#pragma unroll
        for (int k = 0; k < 4; k++) {
            const float v = tile[tx][ty + k * 8];
            const float hi = to_tf32(v);
            const size_t o = (size_t)(c0 + ty + k * 8) * HD + r0 + tx;
            g_wqThi[o] = hi;
            g_wqTlo[o] = to_tf32(v - hi);
        }
    } else {
#pragma unroll
        for (int k = 0; k < 4; k++) {
            const size_t o = (size_t)(r0 + ty + k * 8) * HD + c0 + tx;
            const float v = Wo[o];
            const float hi = to_tf32(v);
            g_wohi[o] = hi;
            g_wolo[o] = to_tf32(v - hi);
        }
    }
}

// ---------------- LayerNorm + surprise + tf32 split -------------------------------
__global__ void ln_kernel(const float* __restrict__ x,
                          const float* __restrict__ gam,
                          const float* __restrict__ bet) {
    __shared__ float sh[256];
    const int row = blockIdx.x, t = threadIdx.x;
    const float* xr = x + (size_t)row * HD;
    float v[4]; float s = 0.f;
#pragma unroll
    for (int i = 0; i < 4; i++) { v[i] = xr[t + i * 256]; s += v[i]; }
    sh[t] = s; __syncthreads();
    for (int o = 128; o > 0; o >>= 1) { if (t < o) sh[t] += sh[t + o]; __syncthreads(); }
    const float mu = sh[0] * (1.f / HD);
    __syncthreads();
    float ss = 0.f;
#pragma unroll
    for (int i = 0; i < 4; i++) { float d = v[i] - mu; ss += d * d; }
    sh[t] = ss; __syncthreads();
    for (int o = 128; o > 0; o >>= 1) { if (t < o) sh[t] += sh[t + o]; __syncthreads(); }
    const float var = sh[0] * (1.f / HD);
    __syncthreads();
    const float inv = rsqrtf(var + 1e-12f);
    float as = 0.f;
#pragma unroll
    for (int i = 0; i < 4; i++) {
        const int c = t + i * 256;
        const float y = (v[i] - mu) * inv * gam[c] + bet[c];
        const float hi = to_tf32(y);
        g_nhi[(size_t)row * HD + c] = hi;
        g_nlo[(size_t)row * HD + c] = to_tf32(y - hi);
        as += fabsf(y);
    }
    sh[t] = as; __syncthreads();
    for (int o = 128; o > 0; o >>= 1) { if (t < o) sh[t] += sh[t + o]; __syncthreads(); }
    if (t == 0) g_surprise[row] = sh[0] * (1.f / HD);
}

// ---------------- top-K (both selections in one kernel) ----------------------------
template <int PER, bool NEG>
__device__ void topk_impl(const float* __restrict__ src,
                          int* __restrict__ oidx, float* __restrict__ oval) {
    __shared__ float sv[1024];
    __shared__ int   si[1024];
    const int t = threadIdx.x;
    float loc[PER];
#pragma unroll
    for (int i = 0; i < PER; i++) { float x = src[t * PER + i]; loc[i] = NEG ? -x : x; }
    for (int k = 0; k < TK; k++) {
        float bv = -CUDART_INF_F; int bi = 0x7fffffff;
#pragma unroll
        for (int i = 0; i < PER; i++)
            if (loc[i] > bv) { bv = loc[i]; bi = t * PER + i; }
        sv[t] = bv; si[t] = bi; __syncthreads();
        for (int o = 512; o > 0; o >>= 1) {
            if (t < o) {
                float ov = sv[t + o]; int oi = si[t + o];
                if (ov > sv[t] || (ov == sv[t] && oi < si[t])) { sv[t] = ov; si[t] = oi; }
            }
            __syncthreads();
        }
        const int win = si[0];
        if (t == 0) { oidx[k] = win; oval[k] = NEG ? -sv[0] : sv[0]; }
        __syncthreads();
        const int rel = win - t * PER;
        if ((unsigned)rel < (unsigned)PER) loc[rel] = -CUDART_INF_F;
    }
}
__global__ void topk2_kernel(const float* __restrict__ imp) {
    if (blockIdx.x == 0) topk_impl<NR / 1024, false>(g_surprise, g_top_idx, g_top_val);
    else                 topk_impl<MMR / 1024, true>(imp, g_slots, g_slot_val);
}

// ---------------- memory materialization -------------------------------------------
__global__ void split_kernel(const float* __restrict__ src,
                             float* __restrict__ hi, float* __restrict__ lo, int n4) {
    const int i = blockIdx.x * blockDim.x + threadIdx.x;
    if (i >= n4) return;
    float4 v = reinterpret_cast<const float4*>(src)[i];
    float4 h, l;
    h.x = to_tf32(v.x); l.x = to_tf32(v.x - h.x);
    h.y = to_tf32(v.y); l.y = to_tf32(v.y - h.y);
    h.z = to_tf32(v.z); l.z = to_tf32(v.z - h.z);
    h.w = to_tf32(v.w); l.w = to_tf32(v.w - h.w);
    reinterpret_cast<float4*>(hi)[i] = h;
    reinterpret_cast<float4*>(lo)[i] = l;
}
__global__ void scatter_mem_kernel() {
    const int j = blockIdx.x;
    if (g_top_val[j] <= THRESHF) return;
    const int src = g_top_idx[j], dst = g_slots[j];
    const int t = threadIdx.x;
    const float4 h = *reinterpret_cast<const float4*>(g_nhi + (size_t)src * HD + t * 4);
    const float4 l = *reinterpret_cast<const float4*>(g_nlo + (size_t)src * HD + t * 4);
    *reinterpret_cast<float4*>(g_mhi + (size_t)dst * HD + t * 4) = h;
    *reinterpret_cast<float4*>(g_mlo + (size_t)dst * HD + t * 4) = l;
}
// transpose in[rows, cols] -> out[cols, rows]
__global__ void transpose_kernel(const float* __restrict__ in, float* __restrict__ out,
                                 int rows, int cols) {
    __shared__ float tile[32][33];
    const int tx = threadIdx.x, ty = threadIdx.y;
    const int c0 = blockIdx.x * 32, r0 = blockIdx.y * 32;
#pragma unroll
    for (int k = 0; k < 4; k++)
        tile[ty + k * 8][tx] = in[(size_t)(r0 + ty + k * 8) * cols + c0 + tx];
    __syncthreads();
#pragma unroll
    for (int k = 0; k < 4; k++)
        out[(size_t)(c0 + ty + k * 8) * rows + r0 + tx] = tile[tx][ty + k * 8];
}
// c[m] = bq . mem[m]
__global__ void cvec_kernel(const float* __restrict__ bq) {
    __shared__ float sh[256];
    const int m = blockIdx.x, t = threadIdx.x;
    float s = 0.f;
#pragma unroll
    for (int i = 0; i < 4; i++) {
        const int o = t + i * 256;
        s += bq[o] * (g_mhi[(size_t)m * HD + o] + g_mlo[(size_t)m * HD + o]);
    }
    sh[t] = s; __syncthreads();
    for (int o = 128; o > 0; o >>= 1) { if (t < o) sh[t] += sh[t + o]; __syncthreads(); }
    if (t == 0) g_cvec[m] = sh[0];
}

// ---------------- softmax in-place on g_sim (rounded attn out) ----------------------
__global__ void softmax_kernel() {
    __shared__ float sh[256];
    const int row = blockIdx.x, t = threadIdx.x;
    float* p = g_sim + (size_t)row * MMR;
    float v[16];
    float mx = -CUDART_INF_F;
#pragma unroll
    for (int i = 0; i < 16; i++) { v[i] = p[t + i * 256]; mx = fmaxf(mx, v[i]); }
    sh[t] = mx; __syncthreads();
    for (int o = 128; o > 0; o >>= 1) { if (t < o) sh[t] = fmaxf(sh[t], sh[t + o]); __syncthreads(); }
    mx = sh[0]; __syncthreads();
    float s = 0.f;
#pragma unroll
    for (int i = 0; i < 16; i++) { v[i] = fexp(v[i] - mx); s += v[i]; }
    sh[t] = s; __syncthreads();
    for (int o = 128; o > 0; o >>= 1) { if (t < o) sh[t] += sh[t + o]; __syncthreads(); }
    const float inv = 1.f / sh[0];
#pragma unroll
    for (int i = 0; i < 16; i++)
        p[t + i * 256] = to_tf32(v[i] * inv);
}

// ---------------- mma.sync tf32 GEMM -------------------------------------------------
// C[M,N] = A[M,K] * B[N,K]^T, both K-major. SPLITQ: 3-product split (Ah+Al)(Bh+Bl).
#define PAD 36
#define TILE_FLOATS (128 * PAD)

__device__ __forceinline__ void g2s_tile(const float* __restrict__ g, int ld,
                                         int row0, int k0, float* __restrict__ s, int tid) {
#pragma unroll
    for (int j = 0; j < 4; j++) {
        const int idx = j * 256 + tid;
        const int r = idx >> 3, c = idx & 7;
        cp16(smem_u32(s + r * PAD + c * 4), g + (size_t)(row0 + r) * ld + k0 + c * 4);
    }
}

template <bool SPLITQ, bool BIAS, bool RES, bool ROUND>
__global__ __launch_bounds__(256, 2) void mma_gemm(
    const float* __restrict__ Ah, const float* __restrict__ Al,
    const float* __restrict__ Bh, const float* __restrict__ Bl,
    float* __restrict__ C, const float* __restrict__ bias, const float* __restrict__ res,
    int Nq, int Kq) {
    extern __shared__ float sm[];
    const int NT = SPLITQ ? 4 : 2;
    const int tid = threadIdx.x;
    const int lane = tid & 31, warp = tid >> 5;
    const int gq = lane >> 2, cq = lane & 3;
    const int wm = (warp >> 1) * 32, wn = (warp & 1) * 64;
    const int m0 = blockIdx.y * 128, n0 = blockIdx.x * 128;
    const int nc = Kq >> 5;

    float acc[2][8][4];
#pragma unroll
    for (int mi = 0; mi < 2; mi++)
#pragma unroll
        for (int ni = 0; ni < 8; ni++)
#pragma unroll
            for (int r = 0; r < 4; r++) acc[mi][ni][r] = 0.f;

#pragma unroll
    for (int p = 0; p < 2; p++) {
        float* base = sm + p * NT * TILE_FLOATS;
        g2s_tile(Ah, Kq, m0, p * 32, base, tid);
        g2s_tile(Bh, Kq, n0, p * 32, base + TILE_FLOATS, tid);
        if (SPLITQ) {
            g2s_tile(Al, Kq, m0, p * 32, base + 2 * TILE_FLOATS, tid);
            g2s_tile(Bl, Kq, n0, p * 32, base + 3 * TILE_FLOATS, tid);
        }
        CP_COMMIT();
    }

    for (int i = 0; i < nc; i++) {
        CP_WAIT1();
        __syncthreads();
        const int s = i & 1;
        const float* base = sm + s * NT * TILE_FLOATS;
        const uint32_t* sA  = reinterpret_cast<const uint32_t*>(base);
        const uint32_t* sB  = reinterpret_cast<const uint32_t*>(base + TILE_FLOATS);
        const uint32_t* sAl = reinterpret_cast<const uint32_t*>(base + 2 * TILE_FLOATS);
        const uint32_t* sBl = reinterpret_cast<const uint32_t*>(base + 3 * TILE_FLOATS);
#pragma unroll
        for (int ks = 0; ks < 4; ks++) {
            const int kc = ks * 8 + cq;
            uint32_t a[2][4], al[2][4];
#pragma unroll
            for (int mi = 0; mi < 2; mi++) {
                const uint32_t* ap = sA + (wm + mi * 16 + gq) * PAD + kc;
                a[mi][0] = ap[0]; a[mi][1] = ap[8 * PAD];
                a[mi][2] = ap[4]; a[mi][3] = ap[8 * PAD + 4];
                if (SPLITQ) {
                    const uint32_t* ap2 = sAl + (wm + mi * 16 + gq) * PAD + kc;
                    al[mi][0] = ap2[0]; al[mi][1] = ap2[8 * PAD];
                    al[mi][2] = ap2[4]; al[mi][3] = ap2[8 * PAD + 4];
                }
            }
#pragma unroll
            for (int ni = 0; ni < 8; ni++) {
                const uint32_t* bp = sB + (wn + ni * 8 + gq) * PAD + kc;
                const uint32_t b0 = bp[0], b1 = bp[4];
#pragma unroll
                for (int mi = 0; mi < 2; mi++) mma8(acc[mi][ni], a[mi], b0, b1);
                if (SPLITQ) {
                    const uint32_t* bp2 = sBl + (wn + ni * 8 + gq) * PAD + kc;
                    const uint32_t bl0 = bp2[0], bl1 = bp2[4];
#pragma unroll
                    for (int mi = 0; mi < 2; mi++) {
                        mma8(acc[mi][ni], a[mi], bl0, bl1);
                        mma8(acc[mi][ni], al[mi], b0, b1);
                    }
                }
            }
        }
        __syncthreads();
        if (i + 2 < nc) {
            float* wbase = sm + s * NT * TILE_FLOATS;
            g2s_tile(Ah, Kq, m0, (i + 2) * 32, wbase, tid);
            g2s_tile(Bh, Kq, n0, (i + 2) * 32, wbase + TILE_FLOATS, tid);
            if (SPLITQ) {
                g2s_tile(Al, Kq, m0, (i + 2) * 32, wbase + 2 * TILE_FLOATS, tid);
                g2s_tile(Bl, Kq, n0, (i + 2) * 32, wbase + 3 * TILE_FLOATS, tid);
            }
        }
        CP_COMMIT();
    }

#pragma unroll
    for (int mi = 0; mi < 2; mi++) {
#pragma unroll
        for (int ni = 0; ni < 8; ni++) {
            const int row = m0 + wm + mi * 16 + gq;
            const int col = n0 + wn + ni * 8 + 2 * cq;
            float2 v0 = make_float2(acc[mi][ni][0], acc[mi][ni][1]);
            float2 v1 = make_float2(acc[mi][ni][2], acc[mi][ni][3]);
            if (BIAS) {
                const float2 bb = *reinterpret_cast<const float2*>(bias + col);
                v0.x += bb.x; v0.y += bb.y; v1.x += bb.x; v1.y += bb.y;
            }
            if (RES) {
                const float2 r0 = *reinterpret_cast<const float2*>(res + (size_t)row * Nq + col);
                const float2 r1 = *reinterpret_cast<const float2*>(res + (size_t)(row + 8) * Nq + col);
                v0.x += r0.x; v0.y += r0.y; v1.x += r1.x; v1.y += r1.y;
            }
            if (ROUND) {
                v0.x = to_tf32(v0.x); v0.y = to_tf32(v0.y);
                v1.x = to_tf32(v1.x); v1.y = to_tf32(v1.y);
            }
            *reinterpret_cast<float2*>(C + (size_t)row * Nq + col) = v0;
            *reinterpret_cast<float2*>(C + (size_t)(row + 8) * Nq + col) = v1;
        }
    }
}

// ---------------- launch ----------------------------------------------------------
#define SMEM_N (2 * 2 * TILE_FLOATS * 4)   // 73728
#define SMEM_S (2 * 4 * TILE_FLOATS * 4)   // 147456

extern "C" void kernel_launch(void* const* d_in, const int* in_sizes, int n_in,
                              void* d_out, int out_size) {
    const float* hidden = (const float*)d_in[0];
    const float* gam    = (const float*)d_in[1];
    const float* bet    = (const float*)d_in[2];
    const float* Wq     = (const float*)d_in[3];
    const float* bq     = (const float*)d_in[4];
    const float* Wo     = (const float*)d_in[5];
    const float* bo     = (const float*)d_in[6];
    const float* memin  = (const float*)d_in[7];
    const float* imp    = (const float*)d_in[8];
    float* out = (float*)d_out;

    float *p_nhi, *p_mhi, *p_mlo, *p_wqThi, *p_wqTlo, *p_wohi, *p_wolo;
    float *p_w2, *p_w3, *p_w3T, *p_sim, *p_cvec;
    cudaGetSymbolAddress((void**)&p_nhi, g_nhi);
    cudaGetSymbolAddress((void**)&p_mhi, g_mhi);     cudaGetSymbolAddress((void**)&p_mlo, g_mlo);
    cudaGetSymbolAddress((void**)&p_wqThi, g_wqThi); cudaGetSymbolAddress((void**)&p_wqTlo, g_wqTlo);
    cudaGetSymbolAddress((void**)&p_wohi, g_wohi);   cudaGetSymbolAddress((void**)&p_wolo, g_wolo);
    cudaGetSymbolAddress((void**)&p_w2, g_w2);       cudaGetSymbolAddress((void**)&p_w3, g_w3);
    cudaGetSymbolAddress((void**)&p_w3T, g_w3T);     cudaGetSymbolAddress((void**)&p_sim, g_sim);
    cudaGetSymbolAddress((void**)&p_cvec, g_cvec);

    cudaFuncSetAttribute((const void*)mma_gemm<true, false, false, true>,
                         cudaFuncAttributeMaxDynamicSharedMemorySize, SMEM_S);
    cudaFuncSetAttribute((const void*)mma_gemm<false, true, false, false>,
                         cudaFuncAttributeMaxDynamicSharedMemorySize, SMEM_N);
    cudaFuncSetAttribute((const void*)mma_gemm<false, true, true, false>,
                         cudaFuncAttributeMaxDynamicSharedMemorySize, SMEM_N);

    // 1) weight prep: Wq^T split, Wo split
    { dim3 b(32, 8), g(32, 32, 2); weight_prep<<<g, b>>>(Wq, Wo); }
    // 2) LayerNorm (split norm) + surprise
    ln_kernel<<<NR, 256>>>(hidden, gam, bet);
    // 3) both top-K selections
    topk2_kernel<<<2, 1024>>>(imp);
    // 4) memory split copy
    split_kernel<<<(MMR * HD / 4 + 255) / 256, 256>>>(memin, p_mhi, p_mlo, MMR * HD / 4);
    // 5) scatter updates
    scatter_mem_kernel<<<TK, 256>>>();
    // 6) W2 = mem @ Wq   [MMR, HD]   (split x split, rounded)   <- ncu target
    {
        dim3 g(HD / 128, MMR / 128);
        mma_gemm<true, false, false, true><<<g, 256, SMEM_S>>>(
            p_mhi, p_mlo, p_wqThi, p_wqTlo, p_w2, nullptr, nullptr, HD, HD);
    }
    // 7) W3 = mem @ Wo^T [MMR, HD]   (split x split, rounded)
    {
        dim3 g(HD / 128, MMR / 128);
        mma_gemm<true, false, false, true><<<g, 256, SMEM_S>>>(
            p_mhi, p_mlo, p_wohi, p_wolo, p_w3, nullptr, nullptr, HD, HD);
    }
    // 8) W3T
    { dim3 b(32, 8), g(HD / 32, MMR / 32); transpose_kernel<<<g, b>>>(p_w3, p_w3T, MMR, HD); }
    // 9) c[m] = bq . mem[m]
    cvec_kernel<<<MMR, 256>>>(bq);
    // 10) sim = norm @ W2^T + c
    {
        dim3 g(MMR / 128, NR / 128);
        mma_gemm<false, true, false, false><<<g, 256, SMEM_N>>>(
            p_nhi, nullptr, p_w2, nullptr, p_sim, p_cvec, nullptr, MMR, HD);
    }
    // 11) softmax in-place (rounded attn)
    softmax_kernel<<<NR, 256>>>();
    // 12) out = attn @ W3 + bo + hidden
    {
        dim3 g(HD / 128, NR / 128);
        mma_gemm<false, true, true, false><<<g, 256, SMEM_N>>>(
            p_sim, nullptr, p_w3T, nullptr, out, bo, hidden, HD, MMR);
    }
}

// round 6
// speedup vs baseline: 4.7890x; 1.5775x over previous
#include <cuda_runtime.h>
#include <cuda_fp16.h>
#include <cstdint>
#include <math_constants.h>

#define HD 1024
#define MMR 4096
#define NR 8192
#define TK 64
#define THRESHF 0.5f

// ---------------- scratch globals ---------------------------------------------
__device__ __half g_nhi[(size_t)NR * HD];
__device__ __half g_nlo[(size_t)NR * HD];
__device__ __half g_mhi[(size_t)MMR * HD];
__device__ __half g_mlo[(size_t)MMR * HD];
__device__ __half g_wqThi[(size_t)HD * HD];
__device__ __half g_wqTlo[(size_t)HD * HD];
__device__ __half g_wohi[(size_t)HD * HD];
__device__ __half g_wolo[(size_t)HD * HD];
__device__ __half g_w2[(size_t)MMR * HD];    // mem @ Wq      [MMR, HD]
__device__ __half g_w3T[(size_t)HD * MMR];   // (mem @ Wo^T)^T = Wo @ mem^T  [HD, MMR]
__device__ __half g_attn[(size_t)NR * MMR];
__device__ float  g_sim[(size_t)NR * MMR];
__device__ float  g_cvec[MMR];
__device__ float  g_surprise[NR];
__device__ int    g_top_idx[TK];
__device__ float  g_top_val[TK];
__device__ int    g_slots[TK];
__device__ float  g_slot_val[TK];

// ---------------- helpers -------------------------------------------------------
__device__ __forceinline__ uint32_t smem_u32(const void* p) {
    uint32_t a;
    asm("{ .reg .u64 t; cvta.to.shared.u64 t, %1; cvt.u32.u64 %0, t; }" : "=r"(a) : "l"(p));
    return a;
}
__device__ __forceinline__ void cp16(uint32_t so, const void* gp) {
    asm volatile("cp.async.cg.shared.global [%0], [%1], 16;" :: "r"(so), "l"(gp) : "memory");
}
#define CP_COMMIT() asm volatile("cp.async.commit_group;" ::: "memory")
#define CP_WAIT1()  asm volatile("cp.async.wait_group 1;" ::: "memory")

__device__ __forceinline__ void mma16(float* d, const uint32_t* a, uint32_t b0, uint32_t b1) {
    asm volatile(
        "mma.sync.aligned.m16n8k16.row.col.f32.f16.f16.f32 "
        "{%0,%1,%2,%3}, {%4,%5,%6,%7}, {%8,%9}, {%0,%1,%2,%3};"
        : "+f"(d[0]), "+f"(d[1]), "+f"(d[2]), "+f"(d[3])
        : "r"(a[0]), "r"(a[1]), "r"(a[2]), "r"(a[3]), "r"(b0), "r"(b1));
}

__device__ __forceinline__ float fexp(float x) {   // e^x on the FMA pipe
    float t = fmaxf(x * 1.44269504088896340736f, -126.f);
    float n = rintf(t);
    float f = t - n;
    float p = 1.8775767e-3f;
    p = fmaf(p, f, 8.9893397e-3f);
    p = fmaf(p, f, 5.5826318e-2f);
    p = fmaf(p, f, 2.4015361e-1f);
    p = fmaf(p, f, 6.9315308e-1f);
    p = fmaf(p, f, 1.0f);
    return p * __int_as_float(((int)n + 127) << 23);
}
__device__ __forceinline__ void split16(float v, __half& hi, __half& lo) {
    hi = __float2half_rn(v);
    lo = __float2half_rn(v - __half2float(hi));
}

// ---------------- weight prep: Wq^T split fp16 + Wo split fp16 --------------------
__global__ void weight_prep(const float* __restrict__ Wq, const float* __restrict__ Wo) {
    __shared__ float tile[32][33];
    const int tx = threadIdx.x, ty = threadIdx.y;
    const int c0 = blockIdx.x * 32, r0 = blockIdx.y * 32;
    if (blockIdx.z == 0) {
#pragma unroll
        for (int k = 0; k < 4; k++)
            tile[ty + k * 8][tx] = Wq[(size_t)(r0 + ty + k * 8) * HD + c0 + tx];
        __syncthreads();
#pragma unroll
        for (int k = 0; k < 4; k++) {
            const size_t o = (size_t)(c0 + ty + k * 8) * HD + r0 + tx;
            split16(tile[tx][ty + k * 8], g_wqThi[o], g_wqTlo[o]);
        }
    } else {
#pragma unroll
        for (int k = 0; k < 4; k++) {
            const size_t o = (size_t)(r0 + ty + k * 8) * HD + c0 + tx;
            split16(Wo[o], g_wohi[o], g_wolo[o]);
        }
    }
}

// ---------------- LayerNorm + surprise + fp16 split --------------------------------
__global__ void ln_kernel(const float* __restrict__ x,
                          const float* __restrict__ gam,
                          const float* __restrict__ bet) {
    __shared__ float sh[256];
    const int row = blockIdx.x, t = threadIdx.x;
    const float* xr = x + (size_t)row * HD;
    float v[4]; float s = 0.f;
#pragma unroll
    for (int i = 0; i < 4; i++) { v[i] = xr[t + i * 256]; s += v[i]; }
    sh[t] = s; __syncthreads();
    for (int o = 128; o > 0; o >>= 1) { if (t < o) sh[t] += sh[t + o]; __syncthreads(); }
    const float mu = sh[0] * (1.f / HD);
    __syncthreads();
    float ss = 0.f;
#pragma unroll
    for (int i = 0; i < 4; i++) { float d = v[i] - mu; ss += d * d; }
    sh[t] = ss; __syncthreads();
    for (int o = 128; o > 0; o >>= 1) { if (t < o) sh[t] += sh[t + o]; __syncthreads(); }
    const float var = sh[0] * (1.f / HD);
    __syncthreads();
    const float inv = rsqrtf(var + 1e-12f);
    float as = 0.f;
#pragma unroll
    for (int i = 0; i < 4; i++) {
        const int c = t + i * 256;
        const float y = (v[i] - mu) * inv * gam[c] + bet[c];
        split16(y, g_nhi[(size_t)row * HD + c], g_nlo[(size_t)row * HD + c]);
        as += fabsf(y);
    }
    sh[t] = as; __syncthreads();
    for (int o = 128; o > 0; o >>= 1) { if (t < o) sh[t] += sh[t + o]; __syncthreads(); }
    if (t == 0) g_surprise[row] = sh[0] * (1.f / HD);
}

// ---------------- top-K (both selections in one kernel) ----------------------------
template <int PER, bool NEG>
__device__ void topk_impl(const float* __restrict__ src,
                          int* __restrict__ oidx, float* __restrict__ oval) {
    __shared__ float sv[1024];
    __shared__ int   si[1024];
    const int t = threadIdx.x;
    float loc[PER];
#pragma unroll
    for (int i = 0; i < PER; i++) { float x = src[t * PER + i]; loc[i] = NEG ? -x : x; }
    for (int k = 0; k < TK; k++) {
        float bv = -CUDART_INF_F; int bi = 0x7fffffff;
#pragma unroll
        for (int i = 0; i < PER; i++)
            if (loc[i] > bv) { bv = loc[i]; bi = t * PER + i; }
        sv[t] = bv; si[t] = bi; __syncthreads();
        for (int o = 512; o > 0; o >>= 1) {
            if (t < o) {
                float ov = sv[t + o]; int oi = si[t + o];
                if (ov > sv[t] || (ov == sv[t] && oi < si[t])) { sv[t] = ov; si[t] = oi; }
            }
            __syncthreads();
        }
        const int win = si[0];
        if (t == 0) { oidx[k] = win; oval[k] = NEG ? -sv[0] : sv[0]; }
        __syncthreads();
        const int rel = win - t * PER;
        if ((unsigned)rel < (unsigned)PER) loc[rel] = -CUDART_INF_F;
    }
}
__global__ void topk2_kernel(const float* __restrict__ imp) {
    if (blockIdx.x == 0) topk_impl<NR / 1024, false>(g_surprise, g_top_idx, g_top_val);
    else                 topk_impl<MMR / 1024, true>(imp, g_slots, g_slot_val);
}

// ---------------- memory materialization -------------------------------------------
__global__ void split_mem_kernel(const float* __restrict__ src, int n4) {
    const int i = blockIdx.x * blockDim.x + threadIdx.x;
    if (i >= n4) return;
    const float4 v = reinterpret_cast<const float4*>(src)[i];
    __half h[4], l[4];
    split16(v.x, h[0], l[0]); split16(v.y, h[1], l[1]);
    split16(v.z, h[2], l[2]); split16(v.w, h[3], l[3]);
    reinterpret_cast<uint2*>(g_mhi)[i] = *reinterpret_cast<uint2*>(h);
    reinterpret_cast<uint2*>(g_mlo)[i] = *reinterpret_cast<uint2*>(l);
}
__global__ void scatter_mem_kernel() {
    const int j = blockIdx.x;
    if (g_top_val[j] <= THRESHF) return;
    const int src = g_top_idx[j], dst = g_slots[j];
    const int t = threadIdx.x;   // 256 threads x uint2 (4 halves)
    const uint2 h = reinterpret_cast<const uint2*>(g_nhi + (size_t)src * HD)[t];
    const uint2 l = reinterpret_cast<const uint2*>(g_nlo + (size_t)src * HD)[t];
    reinterpret_cast<uint2*>(g_mhi + (size_t)dst * HD)[t] = h;
    reinterpret_cast<uint2*>(g_mlo + (size_t)dst * HD)[t] = l;
}
// c[m] = bq . mem[m]
__global__ void cvec_kernel(const float* __restrict__ bq) {
    __shared__ float sh[256];
    const int m = blockIdx.x, t = threadIdx.x;
    float s = 0.f;
#pragma unroll
    for (int i = 0; i < 4; i++) {
        const int o = t + i * 256;
        s += bq[o] * (__half2float(g_mhi[(size_t)m * HD + o]) +
                      __half2float(g_mlo[(size_t)m * HD + o]));
    }
    sh[t] = s; __syncthreads();
    for (int o = 128; o > 0; o >>= 1) { if (t < o) sh[t] += sh[t + o]; __syncthreads(); }
    if (t == 0) g_cvec[m] = sh[0];
}

// ---------------- softmax: g_sim (fp32) -> g_attn (fp16) ----------------------------
__global__ void softmax_kernel() {
    __shared__ float sh[256];
    const int row = blockIdx.x, t = threadIdx.x;
    const float* p = g_sim + (size_t)row * MMR;
    float v[16];
    float mx = -CUDART_INF_F;
#pragma unroll
    for (int i = 0; i < 16; i++) { v[i] = p[t + i * 256]; mx = fmaxf(mx, v[i]); }
    sh[t] = mx; __syncthreads();
    for (int o = 128; o > 0; o >>= 1) { if (t < o) sh[t] = fmaxf(sh[t], sh[t + o]); __syncthreads(); }
    mx = sh[0]; __syncthreads();
    float s = 0.f;
#pragma unroll
    for (int i = 0; i < 16; i++) { v[i] = fexp(v[i] - mx); s += v[i]; }
    sh[t] = s; __syncthreads();
    for (int o = 128; o > 0; o >>= 1) { if (t < o) sh[t] += sh[t + o]; __syncthreads(); }
    const float inv = 1.f / sh[0];
#pragma unroll
    for (int i = 0; i < 16; i++)
        g_attn[(size_t)row * MMR + t + i * 256] = __float2half_rn(v[i] * inv);
}

// ---------------- fp16 mma GEMM ------------------------------------------------------
// C[M,N] = A[M,K] * B[N,K]^T, K-major fp16. SPLIT: 3-product (Ah+Al)(Bh+Bl).
#define RSTRIDE 40                    // halves per smem row (20 words, conflict-free)
#define TILE_HALVES (128 * RSTRIDE)   // KC = 32 halves per stage

__device__ __forceinline__ void g2s_h(const __half* __restrict__ g, int ldh,
                                      int row0, int k0, __half* __restrict__ s, int tid) {
#pragma unroll
    for (int j = 0; j < 2; j++) {
        const int idx = j * 256 + tid;
        const int r = idx >> 2, c = idx & 3;
        cp16(smem_u32(s + r * RSTRIDE + c * 8), g + (size_t)(row0 + r) * ldh + k0 + c * 8);
    }
}

template <bool SPLIT, bool OUTHALF, bool BIAS, bool RES>
__global__ __launch_bounds__(256, 2) void hgemm(
    const __half* __restrict__ Ah, const __half* __restrict__ Al,
    const __half* __restrict__ Bh, const __half* __restrict__ Bl,
    float* __restrict__ Cf, __half* __restrict__ Ch,
    const float* __restrict__ bias, const float* __restrict__ res,
    int Nq, int Kq) {
    extern __shared__ __half sm[];
    const int NT = SPLIT ? 4 : 2;
    const int tid = threadIdx.x;
    const int lane = tid & 31, warp = tid >> 5;
    const int gq = lane >> 2, cq = lane & 3;
    const int wm = (warp >> 1) * 32, wn = (warp & 1) * 64;
    const int m0 = blockIdx.y * 128, n0 = blockIdx.x * 128;
    const int nc = Kq >> 5;

    float acc[2][8][4];
#pragma unroll
    for (int mi = 0; mi < 2; mi++)
#pragma unroll
        for (int ni = 0; ni < 8; ni++)
#pragma unroll
            for (int r = 0; r < 4; r++) acc[mi][ni][r] = 0.f;

#pragma unroll
    for (int p = 0; p < 2; p++) {
        __half* base = sm + p * NT * TILE_HALVES;
        g2s_h(Ah, Kq, m0, p * 32, base, tid);
        g2s_h(Bh, Kq, n0, p * 32, base + TILE_HALVES, tid);
        if (SPLIT) {
            g2s_h(Al, Kq, m0, p * 32, base + 2 * TILE_HALVES, tid);
            g2s_h(Bl, Kq, n0, p * 32, base + 3 * TILE_HALVES, tid);
        }
        CP_COMMIT();
    }

    for (int i = 0; i < nc; i++) {
        CP_WAIT1();
        __syncthreads();
        const int s = i & 1;
        const __half* base = sm + s * NT * TILE_HALVES;
        const uint32_t* sA  = reinterpret_cast<const uint32_t*>(base);
        const uint32_t* sB  = reinterpret_cast<const uint32_t*>(base + TILE_HALVES);
        const uint32_t* sAl = reinterpret_cast<const uint32_t*>(base + 2 * TILE_HALVES);
        const uint32_t* sBl = reinterpret_cast<const uint32_t*>(base + 3 * TILE_HALVES);
#pragma unroll
        for (int ks = 0; ks < 2; ks++) {          // two m16n8k16 steps per 32-half chunk
            const int kc = ks * 8 + cq;
            uint32_t a[2][4], al[2][4];
#pragma unroll
            for (int mi = 0; mi < 2; mi++) {
                const uint32_t* ap = sA + (wm + mi * 16 + gq) * 20 + kc;
                a[mi][0] = ap[0]; a[mi][1] = ap[8 * 20];
                a[mi][2] = ap[4]; a[mi][3] = ap[8 * 20 + 4];
                if (SPLIT) {
                    const uint32_t* ap2 = sAl + (wm + mi * 16 + gq) * 20 + kc;
                    al[mi][0] = ap2[0]; al[mi][1] = ap2[8 * 20];
                    al[mi][2] = ap2[4]; al[mi][3] = ap2[8 * 20 + 4];
                }
            }
#pragma unroll
            for (int ni = 0; ni < 8; ni++) {
                const uint32_t* bp = sB + (wn + ni * 8 + gq) * 20 + kc;
                const uint32_t b0 = bp[0], b1 = bp[4];
#pragma unroll
                for (int mi = 0; mi < 2; mi++) mma16(acc[mi][ni], a[mi], b0, b1);
                if (SPLIT) {
                    const uint32_t* bp2 = sBl + (wn + ni * 8 + gq) * 20 + kc;
                    const uint32_t bl0 = bp2[0], bl1 = bp2[4];
#pragma unroll
                    for (int mi = 0; mi < 2; mi++) {
                        mma16(acc[mi][ni], a[mi], bl0, bl1);
                        mma16(acc[mi][ni], al[mi], b0, b1);
                    }
                }
            }
        }
        __syncthreads();
        if (i + 2 < nc) {
            __half* wbase = sm + s * NT * TILE_HALVES;
            g2s_h(Ah, Kq, m0, (i + 2) * 32, wbase, tid);
            g2s_h(Bh, Kq, n0, (i + 2) * 32, wbase + TILE_HALVES, tid);
            if (SPLIT) {
                g2s_h(Al, Kq, m0, (i + 2) * 32, wbase + 2 * TILE_HALVES, tid);
                g2s_h(Bl, Kq, n0, (i + 2) * 32, wbase + 3 * TILE_HALVES, tid);
            }
        }
        CP_COMMIT();
    }

#pragma unroll
    for (int mi = 0; mi < 2; mi++) {
#pragma unroll
        for (int ni = 0; ni < 8; ni++) {
            const int row = m0 + wm + mi * 16 + gq;
            const int col = n0 + wn + ni * 8 + 2 * cq;
            float2 v0 = make_float2(acc[mi][ni][0], acc[mi][ni][1]);
            float2 v1 = make_float2(acc[mi][ni][2], acc[mi][ni][3]);
            if (BIAS) {
                const float2 bb = *reinterpret_cast<const float2*>(bias + col);
                v0.x += bb.x; v0.y += bb.y; v1.x += bb.x; v1.y += bb.y;
            }
            if (RES) {
                const float2 r0 = *reinterpret_cast<const float2*>(res + (size_t)row * Nq + col);
                const float2 r1 = *reinterpret_cast<const float2*>(res + (size_t)(row + 8) * Nq + col);
                v0.x += r0.x; v0.y += r0.y; v1.x += r1.x; v1.y += r1.y;
            }
            if (OUTHALF) {
                *reinterpret_cast<__half2*>(Ch + (size_t)row * Nq + col) =
                    __floats2half2_rn(v0.x, v0.y);
                *reinterpret_cast<__half2*>(Ch + (size_t)(row + 8) * Nq + col) =
                    __floats2half2_rn(v1.x, v1.y);
            } else {
                *reinterpret_cast<float2*>(Cf + (size_t)row * Nq + col) = v0;
                *reinterpret_cast<float2*>(Cf + (size_t)(row + 8) * Nq + col) = v1;
            }
        }
    }
}

// ---------------- launch ----------------------------------------------------------
#define SMEM_N (2 * 2 * TILE_HALVES * 2)   // 40960
#define SMEM_S (2 * 4 * TILE_HALVES * 2)   // 81920

extern "C" void kernel_launch(void* const* d_in, const int* in_sizes, int n_in,
                              void* d_out, int out_size) {
    const float* hidden = (const float*)d_in[0];
    const float* gam    = (const float*)d_in[1];
    const float* bet    = (const float*)d_in[2];
    const float* Wq     = (const float*)d_in[3];
    const float* bq     = (const float*)d_in[4];
    const float* Wo     = (const float*)d_in[5];
    const float* bo     = (const float*)d_in[6];
    const float* memin  = (const float*)d_in[7];
    const float* imp    = (const float*)d_in[8];
    float* out = (float*)d_out;

    __half *p_nhi, *p_mhi, *p_mlo, *p_wqThi, *p_wqTlo, *p_wohi, *p_wolo;
    __half *p_w2, *p_w3T, *p_attn;
    float *p_sim, *p_cvec;
    cudaGetSymbolAddress((void**)&p_nhi, g_nhi);
    cudaGetSymbolAddress((void**)&p_mhi, g_mhi);     cudaGetSymbolAddress((void**)&p_mlo, g_mlo);
    cudaGetSymbolAddress((void**)&p_wqThi, g_wqThi); cudaGetSymbolAddress((void**)&p_wqTlo, g_wqTlo);
    cudaGetSymbolAddress((void**)&p_wohi, g_wohi);   cudaGetSymbolAddress((void**)&p_wolo, g_wolo);
    cudaGetSymbolAddress((void**)&p_w2, g_w2);       cudaGetSymbolAddress((void**)&p_w3T, g_w3T);
    cudaGetSymbolAddress((void**)&p_attn, g_attn);   cudaGetSymbolAddress((void**)&p_sim, g_sim);
    cudaGetSymbolAddress((void**)&p_cvec, g_cvec);

    cudaFuncSetAttribute((const void*)hgemm<true, true, false, false>,
                         cudaFuncAttributeMaxDynamicSharedMemorySize, SMEM_S);
    cudaFuncSetAttribute((const void*)hgemm<false, false, true, false>,
                         cudaFuncAttributeMaxDynamicSharedMemorySize, SMEM_N);
    cudaFuncSetAttribute((const void*)hgemm<false, false, true, true>,
                         cudaFuncAttributeMaxDynamicSharedMemorySize, SMEM_N);

    // 1) weight prep: Wq^T split fp16 + Wo split fp16
    { dim3 b(32, 8), g(32, 32, 2); weight_prep<<<g, b>>>(Wq, Wo); }
    // 2) LayerNorm (split fp16 norm) + surprise
    ln_kernel<<<NR, 256>>>(hidden, gam, bet);
    // 3) both top-K selections
    topk2_kernel<<<2, 1024>>>(imp);
    // 4) memory split fp16 copy
    split_mem_kernel<<<(MMR * HD / 4 + 255) / 256, 256>>>(memin, MMR * HD / 4);
    // 5) scatter updates
    scatter_mem_kernel<<<TK, 256>>>();
    // 6) W2 = mem @ Wq   [MMR, HD]   (split x split -> fp16)
    {
        dim3 g(HD / 128, MMR / 128);
        hgemm<true, true, false, false><<<g, 256, SMEM_S>>>(
            p_mhi, p_mlo, p_wqThi, p_wqTlo, nullptr, p_w2, nullptr, nullptr, HD, HD);
    }
    // 7) W3T = Wo @ mem^T [HD, MMR]  (split x split -> fp16, no transpose needed)
    {
        dim3 g(MMR / 128, HD / 128);
        hgemm<true, true, false, false><<<g, 256, SMEM_S>>>(
            p_wohi, p_wolo, p_mhi, p_mlo, nullptr, p_w3T, nullptr, nullptr, MMR, HD);
    }
    // 8) c[m] = bq . mem[m]
    cvec_kernel<<<MMR, 256>>>(bq);
    // 9) sim = norm_hi @ W2^T + c   (fp16 single-pass -> fp32)
    {
        dim3 g(MMR / 128, NR / 128);
        hgemm<false, false, true, false><<<g, 256, SMEM_N>>>(
            p_nhi, nullptr, p_w2, nullptr, p_sim, nullptr, p_cvec, nullptr, MMR, HD);
    }
    // 10) softmax -> fp16 attn
    softmax_kernel<<<NR, 256>>>();
    // 11) out = attn @ W3T^T + bo + hidden   (fp16 single-pass -> fp32)
    {
        dim3 g(HD / 128, NR / 128);
        hgemm<false, false, true, true><<<g, 256, SMEM_N>>>(
            p_attn, nullptr, p_w3T, nullptr, out, nullptr, bo, hidden, HD, MMR);
    }
}